// round 1
// baseline (speedup 1.0000x reference)
#include <cuda_runtime.h>

// Problem dims
#define BB       4096
#define DIN      784
#define DZ       128
#define NTRIALS  256
#define BZ       (BB * DZ)

// Scratch: 1/rate per (b,z). __device__ global => no allocations.
__device__ float g_inv_rate[BZ];

// ---------------------------------------------------------------------------
// Tiled fp32 GEMM: C[M,N] = epilogue(A[M,K] @ Bm[K,N] + bias[n])
// BM=64, BN=64, BK=16, 256 threads, 4x4 register tile per thread.
// MODE 0: du = min(acc+bias,5) -> out ; also  g_inv_rate = 1/(exp(min(du+min(prior,5),5))+1e-6)
// MODE 1: y  = sigmoid(acc+bias) -> out
// Assumes M%64==0, K%16==0 (true for both calls). N guarded.
// ---------------------------------------------------------------------------
template <int MODE>
__global__ __launch_bounds__(256)
void gemm_kernel(const float* __restrict__ A,
                 const float* __restrict__ Bm,
                 const float* __restrict__ bias,
                 const float* __restrict__ prior,
                 float* __restrict__ out,
                 int M, int N, int K)
{
    const int BM = 64, BN = 64, BK = 16;
    __shared__ float As[BK][BM];      // transposed A tile
    __shared__ float Bs[BK][BN];

    const int tid = threadIdx.x;                 // 0..255
    const int tx  = tid & 15;                    // n-direction
    const int ty  = tid >> 4;                    // m-direction
    const int m0  = blockIdx.y * BM;
    const int n0  = blockIdx.x * BN;

    // A tile load mapping: 256 threads * float4 = 1024 floats = 64x16
    const int a_m = tid >> 2;                    // 0..63
    const int a_k = (tid & 3) * 4;               // 0,4,8,12
    // B tile load mapping: 16 rows(k) x 64 cols(n)
    const int b_k = tid >> 4;                    // 0..15
    const int b_n = (tid & 15) * 4;              // 0..60

    float acc[4][4];
    #pragma unroll
    for (int i = 0; i < 4; i++)
        #pragma unroll
        for (int j = 0; j < 4; j++) acc[i][j] = 0.f;

    for (int k0 = 0; k0 < K; k0 += BK) {
        // --- load A tile (always in-bounds: M%64==0, K%16==0) ---
        float4 av = *(const float4*)&A[(size_t)(m0 + a_m) * K + k0 + a_k];
        As[a_k + 0][a_m] = av.x;
        As[a_k + 1][a_m] = av.y;
        As[a_k + 2][a_m] = av.z;
        As[a_k + 3][a_m] = av.w;

        // --- load B tile with n-guard ---
        const int gn = n0 + b_n;
        float4 bv;
        if (gn + 3 < N) {
            bv = *(const float4*)&Bm[(size_t)(k0 + b_k) * N + gn];
        } else {
            bv.x = (gn + 0 < N) ? Bm[(size_t)(k0 + b_k) * N + gn + 0] : 0.f;
            bv.y = (gn + 1 < N) ? Bm[(size_t)(k0 + b_k) * N + gn + 1] : 0.f;
            bv.z = (gn + 2 < N) ? Bm[(size_t)(k0 + b_k) * N + gn + 2] : 0.f;
            bv.w = (gn + 3 < N) ? Bm[(size_t)(k0 + b_k) * N + gn + 3] : 0.f;
        }
        *(float4*)&Bs[b_k][b_n] = bv;

        __syncthreads();

        #pragma unroll
        for (int k = 0; k < BK; k++) {
            float4 a4 = *(const float4*)&As[k][ty * 4];
            float4 b4 = *(const float4*)&Bs[k][tx * 4];
            float ar[4] = {a4.x, a4.y, a4.z, a4.w};
            float br[4] = {b4.x, b4.y, b4.z, b4.w};
            #pragma unroll
            for (int i = 0; i < 4; i++)
                #pragma unroll
                for (int j = 0; j < 4; j++)
                    acc[i][j] = fmaf(ar[i], br[j], acc[i][j]);
        }
        __syncthreads();
    }

    // --- epilogue ---
    #pragma unroll
    for (int i = 0; i < 4; i++) {
        const int m = m0 + ty * 4 + i;
        #pragma unroll
        for (int j = 0; j < 4; j++) {
            const int n = n0 + tx * 4 + j;
            if (n >= N) continue;
            float v = acc[i][j] + bias[n];
            if (MODE == 0) {
                float du = fminf(v, 5.0f);
                out[(size_t)m * N + n] = du;
                float lr = fminf(du + fminf(prior[n], 5.0f), 5.0f);
                g_inv_rate[m * DZ + n] = 1.0f / (__expf(lr) + 1e-6f);
            } else {
                float ex = __expf(-v);
                out[(size_t)m * N + n] = __fdividef(1.0f, 1.0f + ex);
            }
        }
    }
}

// ---------------------------------------------------------------------------
// Exponential-race kernel: one thread per (b,z).
//   e_t = -log(1-u_t); times = cumsum(e_t/rate); z = sum sigmoid(1-times)
// Early exit: terms are strictly decreasing (times monotone), so when the
// current term s <= z_acc*1e-8, the remaining tail is < 255*s < 2.6e-6 * z
// relative. Checked every 4 iterations to keep loads batched (MLP=4).
// ---------------------------------------------------------------------------
__global__ __launch_bounds__(256)
void race_kernel(const float* __restrict__ u, float* __restrict__ zout)
{
    const int i = blockIdx.x * blockDim.x + threadIdx.x;   // (b*128 + z)
    const float inv_rate = g_inv_rate[i];
    const float* up = u + i;

    float times = 0.f, zacc = 0.f, s = 0.f;

    for (int t0 = 0; t0 < NTRIALS; t0 += 4) {
        #pragma unroll
        for (int j = 0; j < 4; j++) {
            float uv = up[(size_t)(t0 + j) * BZ];
            float e  = -__logf(1.0f - uv);
            times   += e * inv_rate;
            float ex = __expf(times - 1.0f);       // exp(-(1-times))
            s        = __fdividef(1.0f, 1.0f + ex);
            zacc    += s;
        }
        if (s <= zacc * 1e-8f + 1e-35f) break;     // tail < 2.6e-6 relative
    }
    zout[i] = zacc;
}

// ---------------------------------------------------------------------------
// Launch: du -> d_out[0:BZ], z -> d_out[BZ:2BZ], y -> d_out[2BZ:2BZ+B*DIN]
// Input order: x, u, W_enc, b_enc, W_dec, b_dec, prior
// ---------------------------------------------------------------------------
extern "C" void kernel_launch(void* const* d_in, const int* in_sizes, int n_in,
                              void* d_out, int out_size)
{
    const float* x     = (const float*)d_in[0];
    const float* u     = (const float*)d_in[1];
    const float* W_enc = (const float*)d_in[2];
    const float* b_enc = (const float*)d_in[3];
    const float* W_dec = (const float*)d_in[4];
    const float* b_dec = (const float*)d_in[5];
    const float* prior = (const float*)d_in[6];

    float* out_du = (float*)d_out;
    float* out_z  = out_du + (size_t)BZ;
    float* out_y  = out_z  + (size_t)BZ;

    // 1) encoder GEMM: du + inv_rate
    {
        dim3 grid((DZ + 63) / 64, BB / 64);
        gemm_kernel<0><<<grid, 256>>>(x, W_enc, b_enc, prior, out_du,
                                      BB, DZ, DIN);
    }
    // 2) exponential race -> z
    {
        race_kernel<<<BZ / 256, 256>>>(u, out_z);
    }
    // 3) decoder GEMM: y = sigmoid(z @ W_dec + b_dec)
    {
        dim3 grid((DIN + 63) / 64, BB / 64);
        gemm_kernel<1><<<grid, 256>>>(out_z, W_dec, b_dec, nullptr, out_y,
                                      BB, DIN, DZ);
    }
}

// round 2
// speedup vs baseline: 1.3272x; 1.3272x over previous
#include <cuda_runtime.h>

// Problem dims
#define BB       4096
#define DIN      784
#define DZ       128
#define NTRIALS  256
#define BZ       (BB * DZ)
#define KSPLIT   4

// Scratch (device globals => no allocations).
__device__ float g_inv_rate[BZ];
__device__ float g_part[KSPLIT][BZ];   // split-K partials for encoder

// ---------------------------------------------------------------------------
// Encoder split-K GEMM: partial[c] = x[M,K-chunk] @ W_enc[K-chunk, DZ]
// BM=64, BN=64, BK=16, 256 threads, 4x4 register tile.
// M=4096, N=128, K=784 are exact multiples -> zero guards.
// grid = (2, 64, KSPLIT). K tiles (49 of BK=16) split 13/12/12/12.
// ---------------------------------------------------------------------------
__global__ __launch_bounds__(256)
void enc_gemm_splitk(const float* __restrict__ A,
                     const float* __restrict__ Bm)
{
    const int BM = 64, BN = 64, BK = 16;
    __shared__ float As[BK][BM];
    __shared__ float Bs[BK][BN];

    const int tid = threadIdx.x;
    const int tx  = tid & 15;
    const int ty  = tid >> 4;
    const int m0  = blockIdx.y * BM;
    const int n0  = blockIdx.x * BN;
    const int chunk = blockIdx.z;

    const int t_start = 12 * chunk + (chunk ? 1 : 0);     // 0,13,25,37
    const int t_end   = (chunk == 0) ? 13 : t_start + 12; // 13,25,37,49

    const int a_m = tid >> 2;
    const int a_k = (tid & 3) * 4;
    const int b_k = tid >> 4;
    const int b_n = (tid & 15) * 4;

    float acc[4][4];
    #pragma unroll
    for (int i = 0; i < 4; i++)
        #pragma unroll
        for (int j = 0; j < 4; j++) acc[i][j] = 0.f;

    for (int t = t_start; t < t_end; t++) {
        const int k0 = t * BK;
        float4 av = *(const float4*)&A[(size_t)(m0 + a_m) * DIN + k0 + a_k];
        As[a_k + 0][a_m] = av.x;
        As[a_k + 1][a_m] = av.y;
        As[a_k + 2][a_m] = av.z;
        As[a_k + 3][a_m] = av.w;

        *(float4*)&Bs[b_k][b_n] =
            *(const float4*)&Bm[(size_t)(k0 + b_k) * DZ + n0 + b_n];

        __syncthreads();

        #pragma unroll
        for (int k = 0; k < BK; k++) {
            float4 a4 = *(const float4*)&As[k][ty * 4];
            float4 b4 = *(const float4*)&Bs[k][tx * 4];
            float ar[4] = {a4.x, a4.y, a4.z, a4.w};
            float br[4] = {b4.x, b4.y, b4.z, b4.w};
            #pragma unroll
            for (int i = 0; i < 4; i++)
                #pragma unroll
                for (int j = 0; j < 4; j++)
                    acc[i][j] = fmaf(ar[i], br[j], acc[i][j]);
        }
        __syncthreads();
    }

    float* dst = g_part[chunk];
    #pragma unroll
    for (int i = 0; i < 4; i++) {
        const int m = m0 + ty * 4 + i;
        float4 v = make_float4(acc[i][0], acc[i][1], acc[i][2], acc[i][3]);
        *(float4*)&dst[(size_t)m * DZ + n0 + tx * 4] = v;
    }
}

// ---------------------------------------------------------------------------
// Encoder epilogue: du = min(sum(partials)+bias, 5); inv_rate from du+prior.
// ---------------------------------------------------------------------------
__global__ __launch_bounds__(256)
void enc_epilogue(const float* __restrict__ bias,
                  const float* __restrict__ prior,
                  float* __restrict__ out_du)
{
    const int i = blockIdx.x * blockDim.x + threadIdx.x;
    const int n = i & (DZ - 1);
    float v = g_part[0][i] + g_part[1][i] + g_part[2][i] + g_part[3][i]
              + bias[n];
    float du = fminf(v, 5.0f);
    out_du[i] = du;
    float lr = fminf(du + fminf(prior[n], 5.0f), 5.0f);
    g_inv_rate[i] = 1.0f / (__expf(lr) + 1e-6f);
}

// ---------------------------------------------------------------------------
// Decoder GEMM (unchanged from R1): y = sigmoid(z @ W_dec + b_dec)
// BM=64, BN=64, BK=16, 256 threads, 4x4 register tile. N guarded (784).
// ---------------------------------------------------------------------------
__global__ __launch_bounds__(256)
void dec_gemm(const float* __restrict__ A,
              const float* __restrict__ Bm,
              const float* __restrict__ bias,
              float* __restrict__ out,
              int M, int N, int K)
{
    const int BM = 64, BN = 64, BK = 16;
    __shared__ float As[BK][BM];
    __shared__ float Bs[BK][BN];

    const int tid = threadIdx.x;
    const int tx  = tid & 15;
    const int ty  = tid >> 4;
    const int m0  = blockIdx.y * BM;
    const int n0  = blockIdx.x * BN;

    const int a_m = tid >> 2;
    const int a_k = (tid & 3) * 4;
    const int b_k = tid >> 4;
    const int b_n = (tid & 15) * 4;

    float acc[4][4];
    #pragma unroll
    for (int i = 0; i < 4; i++)
        #pragma unroll
        for (int j = 0; j < 4; j++) acc[i][j] = 0.f;

    for (int k0 = 0; k0 < K; k0 += BK) {
        float4 av = *(const float4*)&A[(size_t)(m0 + a_m) * K + k0 + a_k];
        As[a_k + 0][a_m] = av.x;
        As[a_k + 1][a_m] = av.y;
        As[a_k + 2][a_m] = av.z;
        As[a_k + 3][a_m] = av.w;

        const int gn = n0 + b_n;
        float4 bv;
        if (gn + 3 < N) {
            bv = *(const float4*)&Bm[(size_t)(k0 + b_k) * N + gn];
        } else {
            bv.x = (gn + 0 < N) ? Bm[(size_t)(k0 + b_k) * N + gn + 0] : 0.f;
            bv.y = (gn + 1 < N) ? Bm[(size_t)(k0 + b_k) * N + gn + 1] : 0.f;
            bv.z = (gn + 2 < N) ? Bm[(size_t)(k0 + b_k) * N + gn + 2] : 0.f;
            bv.w = (gn + 3 < N) ? Bm[(size_t)(k0 + b_k) * N + gn + 3] : 0.f;
        }
        *(float4*)&Bs[b_k][b_n] = bv;

        __syncthreads();

        #pragma unroll
        for (int k = 0; k < BK; k++) {
            float4 a4 = *(const float4*)&As[k][ty * 4];
            float4 b4 = *(const float4*)&Bs[k][tx * 4];
            float ar[4] = {a4.x, a4.y, a4.z, a4.w};
            float br[4] = {b4.x, b4.y, b4.z, b4.w};
            #pragma unroll
            for (int i = 0; i < 4; i++)
                #pragma unroll
                for (int j = 0; j < 4; j++)
                    acc[i][j] = fmaf(ar[i], br[j], acc[i][j]);
        }
        __syncthreads();
    }

    #pragma unroll
    for (int i = 0; i < 4; i++) {
        const int m = m0 + ty * 4 + i;
        #pragma unroll
        for (int j = 0; j < 4; j++) {
            const int n = n0 + tx * 4 + j;
            if (n >= N) continue;
            float v = acc[i][j] + bias[n];
            float ex = __expf(-v);
            out[(size_t)m * N + n] = __fdividef(1.0f, 1.0f + ex);
        }
    }
}

// ---------------------------------------------------------------------------
// Exponential-race kernel (unchanged from R1, rel_err 6.5e-7).
// ---------------------------------------------------------------------------
__global__ __launch_bounds__(256)
void race_kernel(const float* __restrict__ u, float* __restrict__ zout)
{
    const int i = blockIdx.x * blockDim.x + threadIdx.x;
    const float inv_rate = g_inv_rate[i];
    const float* up = u + i;

    float times = 0.f, zacc = 0.f, s = 0.f;

    for (int t0 = 0; t0 < NTRIALS; t0 += 4) {
        #pragma unroll
        for (int j = 0; j < 4; j++) {
            float uv = up[(size_t)(t0 + j) * BZ];
            float e  = -__logf(1.0f - uv);
            times   += e * inv_rate;
            float ex = __expf(times - 1.0f);
            s        = __fdividef(1.0f, 1.0f + ex);
            zacc    += s;
        }
        if (s <= zacc * 1e-8f + 1e-35f) break;
    }
    zout[i] = zacc;
}

// ---------------------------------------------------------------------------
// Launch. Input order: x, u, W_enc, b_enc, W_dec, b_dec, prior
// Output: du [BZ] | z [BZ] | y [B*DIN]
// ---------------------------------------------------------------------------
extern "C" void kernel_launch(void* const* d_in, const int* in_sizes, int n_in,
                              void* d_out, int out_size)
{
    const float* x     = (const float*)d_in[0];
    const float* u     = (const float*)d_in[1];
    const float* W_enc = (const float*)d_in[2];
    const float* b_enc = (const float*)d_in[3];
    const float* W_dec = (const float*)d_in[4];
    const float* b_dec = (const float*)d_in[5];
    const float* prior = (const float*)d_in[6];

    float* out_du = (float*)d_out;
    float* out_z  = out_du + (size_t)BZ;
    float* out_y  = out_z  + (size_t)BZ;

    // 1) encoder split-K GEMM + epilogue
    {
        dim3 grid(DZ / 64, BB / 64, KSPLIT);
        enc_gemm_splitk<<<grid, 256>>>(x, W_enc);
        enc_epilogue<<<BZ / 256, 256>>>(b_enc, prior, out_du);
    }
    // 2) exponential race -> z
    race_kernel<<<BZ / 256, 256>>>(u, out_z);

    // 3) decoder GEMM: y = sigmoid(z @ W_dec + b_dec)
    {
        dim3 grid((DIN + 63) / 64, BB / 64);
        dec_gemm<<<grid, 256>>>(out_z, W_dec, b_dec, out_y, BB, DIN, DZ);
    }
}

// round 3
// speedup vs baseline: 1.5077x; 1.1360x over previous
#include <cuda_runtime.h>

// Problem dims
#define BB       4096
#define DIN      784
#define DZ       128
#define NTRIALS  256
#define BZ       (BB * DZ)
#define KSPLIT   7          // 49 K-tiles of 16 = 7 chunks x 7 tiles, exact

// Scratch (device globals => no allocations).
__device__ float g_part[KSPLIT][BZ];   // split-K partials for encoder

__device__ __forceinline__ float tanhf_fast(float x) {
    float y;
    asm("tanh.approx.f32 %0, %1;" : "=f"(y) : "f"(x));
    return y;
}

// ---------------------------------------------------------------------------
// Encoder split-K GEMM: g_part[c] = x[:, c-chunk] @ W_enc[c-chunk, :]
// BM=128, BN=64, BK=16, 256 threads, 8x4 register tile. All dims exact.
// grid = (DZ/64=2, BB/128=32, KSPLIT=7)
// ---------------------------------------------------------------------------
__global__ __launch_bounds__(256)
void enc_gemm_splitk(const float* __restrict__ A,
                     const float* __restrict__ Bm)
{
    __shared__ float As[16][128];
    __shared__ float Bs[16][64];

    const int tid = threadIdx.x;
    const int tx  = tid & 15;          // n dir: 16 * 4 = 64
    const int ty  = tid >> 4;          // m dir: 16 * 8 = 128
    const int m0  = blockIdx.y * 128;
    const int n0  = blockIdx.x * 64;
    const int chunk = blockIdx.z;

    // A tile load: 128x16 = 2048 floats / 256 thr = 8 = 2 float4
    const int a_m = tid >> 1;          // 0..127
    const int a_k = (tid & 1) * 8;     // 0 or 8
    // B tile load: 16x64 = 1024 / 256 = 4 = 1 float4
    const int b_k = tid >> 4;          // 0..15
    const int b_n = (tid & 15) * 4;

    float acc[8][4];
    #pragma unroll
    for (int i = 0; i < 8; i++)
        #pragma unroll
        for (int j = 0; j < 4; j++) acc[i][j] = 0.f;

    #pragma unroll 1
    for (int t = chunk * 7; t < chunk * 7 + 7; t++) {
        const int k0 = t * 16;

        float4 av0 = *(const float4*)&A[(size_t)(m0 + a_m) * DIN + k0 + a_k];
        float4 av1 = *(const float4*)&A[(size_t)(m0 + a_m) * DIN + k0 + a_k + 4];
        As[a_k + 0][a_m] = av0.x; As[a_k + 1][a_m] = av0.y;
        As[a_k + 2][a_m] = av0.z; As[a_k + 3][a_m] = av0.w;
        As[a_k + 4][a_m] = av1.x; As[a_k + 5][a_m] = av1.y;
        As[a_k + 6][a_m] = av1.z; As[a_k + 7][a_m] = av1.w;

        *(float4*)&Bs[b_k][b_n] =
            *(const float4*)&Bm[(size_t)(k0 + b_k) * DZ + n0 + b_n];

        __syncthreads();

        #pragma unroll
        for (int k = 0; k < 16; k++) {
            float4 a0 = *(const float4*)&As[k][ty * 8];
            float4 a1 = *(const float4*)&As[k][ty * 8 + 4];
            float4 b4 = *(const float4*)&Bs[k][tx * 4];
            float ar[8] = {a0.x, a0.y, a0.z, a0.w, a1.x, a1.y, a1.z, a1.w};
            float br[4] = {b4.x, b4.y, b4.z, b4.w};
            #pragma unroll
            for (int i = 0; i < 8; i++)
                #pragma unroll
                for (int j = 0; j < 4; j++)
                    acc[i][j] = fmaf(ar[i], br[j], acc[i][j]);
        }
        __syncthreads();
    }

    float* dst = g_part[chunk];
    #pragma unroll
    for (int i = 0; i < 8; i++) {
        const int m = m0 + ty * 8 + i;
        float4 v = make_float4(acc[i][0], acc[i][1], acc[i][2], acc[i][3]);
        *(float4*)&dst[(size_t)m * DZ + n0 + tx * 4] = v;
    }
}

// ---------------------------------------------------------------------------
// Fused encoder-epilogue + exponential race. One thread per (b,z).
//   du = min(sum(partials)+bias, 5); rate = exp(min(du+min(prior,5),5))+1e-6
//   e_t = -ln(1-u_t); times = cumsum(e_t/rate); z = sum sigmoid(1-times)
// Base-2 refactor: cum = sum lg2(1-u_t)  =>  times = -ln2*inv_rate*cum
//   sigmoid(1-times) = 0.5 + 0.5*tanh(0.5 + 0.5*ln2*inv_rate*cum)
// Early exit: terms strictly decreasing; when s <= zacc*1e-8 the tail is
// bounded by 255*s < 2.6e-6 relative.
// ---------------------------------------------------------------------------
__global__ __launch_bounds__(256)
void race_kernel(const float* __restrict__ u,
                 const float* __restrict__ bias,
                 const float* __restrict__ prior,
                 float* __restrict__ out_du,
                 float* __restrict__ zout)
{
    const int i = blockIdx.x * blockDim.x + threadIdx.x;
    const int n = i & (DZ - 1);

    float v = g_part[0][i] + g_part[1][i] + g_part[2][i] + g_part[3][i]
            + g_part[4][i] + g_part[5][i] + g_part[6][i] + bias[n];
    float du = fminf(v, 5.0f);
    out_du[i] = du;
    float lr = fminf(du + fminf(prior[n], 5.0f), 5.0f);
    float inv_rate = 1.0f / (__expf(lr) + 1e-6f);
    const float a = 0.34657359f * inv_rate;   // 0.5*ln2*inv_rate

    const float* up = u + i;
    float cum = 0.f, zacc = 0.f, s = 0.f;

    for (int t0 = 0; t0 < NTRIALS; t0 += 4) {
        #pragma unroll
        for (int j = 0; j < 4; j++) {
            float uv = up[(size_t)(t0 + j) * BZ];
            cum += __log2f(1.0f - uv);            // negative, decreasing
            float h  = fmaf(cum, a, 0.5f);        // (1-times)/2
            float th = tanhf_fast(h);
            s = fmaf(0.5f, th, 0.5f);             // sigmoid(1-times)
            zacc += s;
        }
        if (s <= zacc * 1e-8f + 1e-35f) break;
    }
    zout[i] = zacc;
}

// ---------------------------------------------------------------------------
// Decoder GEMM: y = sigmoid(z @ W_dec + b_dec)
// BM=128, BN=64, BK=16, 256 threads, 8x4 register tile. N=784 guarded.
// grid = (13, 32)
// ---------------------------------------------------------------------------
__global__ __launch_bounds__(256)
void dec_gemm(const float* __restrict__ A,
              const float* __restrict__ Bm,
              const float* __restrict__ bias,
              float* __restrict__ out)
{
    const int N = DIN, K = DZ;
    __shared__ float As[16][128];
    __shared__ float Bs[16][64];

    const int tid = threadIdx.x;
    const int tx  = tid & 15;
    const int ty  = tid >> 4;
    const int m0  = blockIdx.y * 128;
    const int n0  = blockIdx.x * 64;

    const int a_m = tid >> 1;
    const int a_k = (tid & 1) * 8;
    const int b_k = tid >> 4;
    const int b_n = (tid & 15) * 4;

    float acc[8][4];
    #pragma unroll
    for (int i = 0; i < 8; i++)
        #pragma unroll
        for (int j = 0; j < 4; j++) acc[i][j] = 0.f;

    #pragma unroll 1
    for (int k0 = 0; k0 < K; k0 += 16) {
        float4 av0 = *(const float4*)&A[(size_t)(m0 + a_m) * K + k0 + a_k];
        float4 av1 = *(const float4*)&A[(size_t)(m0 + a_m) * K + k0 + a_k + 4];
        As[a_k + 0][a_m] = av0.x; As[a_k + 1][a_m] = av0.y;
        As[a_k + 2][a_m] = av0.z; As[a_k + 3][a_m] = av0.w;
        As[a_k + 4][a_m] = av1.x; As[a_k + 5][a_m] = av1.y;
        As[a_k + 6][a_m] = av1.z; As[a_k + 7][a_m] = av1.w;

        const int gn = n0 + b_n;
        float4 bv;
        if (gn + 3 < N) {
            bv = *(const float4*)&Bm[(size_t)(k0 + b_k) * N + gn];
        } else {
            bv.x = (gn + 0 < N) ? Bm[(size_t)(k0 + b_k) * N + gn + 0] : 0.f;
            bv.y = (gn + 1 < N) ? Bm[(size_t)(k0 + b_k) * N + gn + 1] : 0.f;
            bv.z = (gn + 2 < N) ? Bm[(size_t)(k0 + b_k) * N + gn + 2] : 0.f;
            bv.w = (gn + 3 < N) ? Bm[(size_t)(k0 + b_k) * N + gn + 3] : 0.f;
        }
        *(float4*)&Bs[b_k][b_n] = bv;

        __syncthreads();

        #pragma unroll
        for (int k = 0; k < 16; k++) {
            float4 a0 = *(const float4*)&As[k][ty * 8];
            float4 a1 = *(const float4*)&As[k][ty * 8 + 4];
            float4 b4 = *(const float4*)&Bs[k][tx * 4];
            float ar[8] = {a0.x, a0.y, a0.z, a0.w, a1.x, a1.y, a1.z, a1.w};
            float br[4] = {b4.x, b4.y, b4.z, b4.w};
            #pragma unroll
            for (int i = 0; i < 8; i++)
                #pragma unroll
                for (int j = 0; j < 4; j++)
                    acc[i][j] = fmaf(ar[i], br[j], acc[i][j]);
        }
        __syncthreads();
    }

    #pragma unroll
    for (int i = 0; i < 8; i++) {
        const int m = m0 + ty * 8 + i;
        #pragma unroll
        for (int j = 0; j < 4; j++) {
            const int nn = n0 + tx * 4 + j;
            if (nn >= N) continue;
            float vv = acc[i][j] + bias[nn];
            float ex = __expf(-vv);
            out[(size_t)m * N + nn] = __fdividef(1.0f, 1.0f + ex);
        }
    }
}

// ---------------------------------------------------------------------------
// Launch. Input order: x, u, W_enc, b_enc, W_dec, b_dec, prior
// Output: du [BZ] | z [BZ] | y [B*DIN]
// ---------------------------------------------------------------------------
extern "C" void kernel_launch(void* const* d_in, const int* in_sizes, int n_in,
                              void* d_out, int out_size)
{
    const float* x     = (const float*)d_in[0];
    const float* u     = (const float*)d_in[1];
    const float* W_enc = (const float*)d_in[2];
    const float* b_enc = (const float*)d_in[3];
    const float* W_dec = (const float*)d_in[4];
    const float* b_dec = (const float*)d_in[5];
    const float* prior = (const float*)d_in[6];

    float* out_du = (float*)d_out;
    float* out_z  = out_du + (size_t)BZ;
    float* out_y  = out_z  + (size_t)BZ;

    // 1) encoder split-K GEMM
    {
        dim3 grid(DZ / 64, BB / 128, KSPLIT);
        enc_gemm_splitk<<<grid, 256>>>(x, W_enc);
    }
    // 2) fused epilogue + exponential race -> du, z
    race_kernel<<<BZ / 256, 256>>>(u, b_enc, prior, out_du, out_z);

    // 3) decoder GEMM: y = sigmoid(z @ W_dec + b_dec)
    {
        dim3 grid((DIN + 63) / 64, BB / 128);
        dec_gemm<<<grid, 256>>>(out_z, W_dec, b_dec, out_y);
    }
}

// round 4
// speedup vs baseline: 1.8407x; 1.2209x over previous
#include <cuda_runtime.h>

// Problem dims
#define BB       4096
#define DIN      784
#define DZ       128
#define NTRIALS  256
#define BZ       (BB * DZ)
#define KSPLIT   7          // 49 K-tiles of 16 = 7 chunks x 7 tiles, exact

// Scratch (device globals => no allocations).
__device__ float g_part[KSPLIT][BZ];   // split-K partials for encoder

__device__ __forceinline__ float tanhf_fast(float x) {
    float y;
    asm("tanh.approx.f32 %0, %1;" : "=f"(y) : "f"(x));
    return y;
}

// ---------------------------------------------------------------------------
// Encoder split-K GEMM: g_part[c] = x[:, c-chunk] @ W_enc[c-chunk, :]
// BM=128, BN=64, BK=16, 256 threads, 8x4 register tile. All dims exact.
// grid = (DZ/64=2, BB/128=32, KSPLIT=7)
// ---------------------------------------------------------------------------
__global__ __launch_bounds__(256)
void enc_gemm_splitk(const float* __restrict__ A,
                     const float* __restrict__ Bm)
{
    __shared__ float As[16][128];
    __shared__ float Bs[16][64];

    const int tid = threadIdx.x;
    const int tx  = tid & 15;
    const int ty  = tid >> 4;
    const int m0  = blockIdx.y * 128;
    const int n0  = blockIdx.x * 64;
    const int chunk = blockIdx.z;

    const int a_m = tid >> 1;
    const int a_k = (tid & 1) * 8;
    const int b_k = tid >> 4;
    const int b_n = (tid & 15) * 4;

    float acc[8][4];
    #pragma unroll
    for (int i = 0; i < 8; i++)
        #pragma unroll
        for (int j = 0; j < 4; j++) acc[i][j] = 0.f;

    #pragma unroll 1
    for (int t = chunk * 7; t < chunk * 7 + 7; t++) {
        const int k0 = t * 16;

        float4 av0 = *(const float4*)&A[(size_t)(m0 + a_m) * DIN + k0 + a_k];
        float4 av1 = *(const float4*)&A[(size_t)(m0 + a_m) * DIN + k0 + a_k + 4];
        As[a_k + 0][a_m] = av0.x; As[a_k + 1][a_m] = av0.y;
        As[a_k + 2][a_m] = av0.z; As[a_k + 3][a_m] = av0.w;
        As[a_k + 4][a_m] = av1.x; As[a_k + 5][a_m] = av1.y;
        As[a_k + 6][a_m] = av1.z; As[a_k + 7][a_m] = av1.w;

        *(float4*)&Bs[b_k][b_n] =
            *(const float4*)&Bm[(size_t)(k0 + b_k) * DZ + n0 + b_n];

        __syncthreads();

        #pragma unroll
        for (int k = 0; k < 16; k++) {
            float4 a0 = *(const float4*)&As[k][ty * 8];
            float4 a1 = *(const float4*)&As[k][ty * 8 + 4];
            float4 b4 = *(const float4*)&Bs[k][tx * 4];
            float ar[8] = {a0.x, a0.y, a0.z, a0.w, a1.x, a1.y, a1.z, a1.w};
            float br[4] = {b4.x, b4.y, b4.z, b4.w};
            #pragma unroll
            for (int i = 0; i < 8; i++)
                #pragma unroll
                for (int j = 0; j < 4; j++)
                    acc[i][j] = fmaf(ar[i], br[j], acc[i][j]);
        }
        __syncthreads();
    }

    float* dst = g_part[chunk];
    #pragma unroll
    for (int i = 0; i < 8; i++) {
        const int m = m0 + ty * 8 + i;
        float4 v = make_float4(acc[i][0], acc[i][1], acc[i][2], acc[i][3]);
        *(float4*)&dst[(size_t)m * DZ + n0 + tx * 4] = v;
    }
}

// ---------------------------------------------------------------------------
// Fused encoder-epilogue + exponential race. One thread per (b,z).
// Software-pipelined: prefetch next 8 trials while computing current 8.
// Warp-uniform early exit (loads are line-exact; per-lane exit saves nothing).
// Base-2 refactor: cum = sum lg2(1-u_t)  =>  times = -ln2*inv_rate*cum
//   sigmoid(1-times) = 0.5 + 0.5*tanh(0.5 + 0.5*ln2*inv_rate*cum)
// Tail bound at exit: 255*s <= 255*1e-7*zacc = 2.6e-5 relative.
// ---------------------------------------------------------------------------
__global__ __launch_bounds__(256)
void race_kernel(const float* __restrict__ u,
                 const float* __restrict__ bias,
                 const float* __restrict__ prior,
                 float* __restrict__ out_du,
                 float* __restrict__ zout)
{
    const int i = blockIdx.x * blockDim.x + threadIdx.x;
    const int n = i & (DZ - 1);

    float v = g_part[0][i] + g_part[1][i] + g_part[2][i] + g_part[3][i]
            + g_part[4][i] + g_part[5][i] + g_part[6][i] + bias[n];
    float du = fminf(v, 5.0f);
    out_du[i] = du;
    float lr = fminf(du + fminf(prior[n], 5.0f), 5.0f);
    float inv_rate = 1.0f / (__expf(lr) + 1e-6f);
    const float a = 0.34657359f * inv_rate;   // 0.5*ln2*inv_rate

    const float* up = u + i;

    float cum = 0.f, zacc = 0.f;
    float buf[8];
    #pragma unroll
    for (int j = 0; j < 8; j++) buf[j] = up[(size_t)j * BZ];

    #pragma unroll 1
    for (int t0 = 0; t0 < NTRIALS; t0 += 8) {
        // prefetch next batch (issues before compute; overlaps DRAM latency)
        float nbuf[8];
        if (t0 + 8 < NTRIALS) {
            #pragma unroll
            for (int j = 0; j < 8; j++)
                nbuf[j] = up[(size_t)(t0 + 8 + j) * BZ];
        }

        float s = 0.f;
        #pragma unroll
        for (int j = 0; j < 8; j++) {
            cum += __log2f(1.0f - buf[j]);          // negative, decreasing
            float h  = fmaf(cum, a, 0.5f);          // (1-times)/2
            s = fmaf(0.5f, tanhf_fast(h), 0.5f);    // sigmoid(1-times)
            zacc += s;
        }

        if (__all_sync(0xFFFFFFFFu, s <= zacc * 1e-7f + 1e-30f)) break;

        #pragma unroll
        for (int j = 0; j < 8; j++) buf[j] = nbuf[j];
    }
    zout[i] = zacc;
}

// ---------------------------------------------------------------------------
// Decoder GEMM: y = sigmoid(z @ W_dec + b_dec)
// BM=128, BN=64, BK=16, 256 threads, 8x4 register tile. N=784 guarded.
// ---------------------------------------------------------------------------
__global__ __launch_bounds__(256)
void dec_gemm(const float* __restrict__ A,
              const float* __restrict__ Bm,
              const float* __restrict__ bias,
              float* __restrict__ out)
{
    const int N = DIN, K = DZ;
    __shared__ float As[16][128];
    __shared__ float Bs[16][64];

    const int tid = threadIdx.x;
    const int tx  = tid & 15;
    const int ty  = tid >> 4;
    const int m0  = blockIdx.y * 128;
    const int n0  = blockIdx.x * 64;

    const int a_m = tid >> 1;
    const int a_k = (tid & 1) * 8;
    const int b_k = tid >> 4;
    const int b_n = (tid & 15) * 4;

    float acc[8][4];
    #pragma unroll
    for (int i = 0; i < 8; i++)
        #pragma unroll
        for (int j = 0; j < 4; j++) acc[i][j] = 0.f;

    #pragma unroll 1
    for (int k0 = 0; k0 < K; k0 += 16) {
        float4 av0 = *(const float4*)&A[(size_t)(m0 + a_m) * K + k0 + a_k];
        float4 av1 = *(const float4*)&A[(size_t)(m0 + a_m) * K + k0 + a_k + 4];
        As[a_k + 0][a_m] = av0.x; As[a_k + 1][a_m] = av0.y;
        As[a_k + 2][a_m] = av0.z; As[a_k + 3][a_m] = av0.w;
        As[a_k + 4][a_m] = av1.x; As[a_k + 5][a_m] = av1.y;
        As[a_k + 6][a_m] = av1.z; As[a_k + 7][a_m] = av1.w;

        const int gn = n0 + b_n;
        float4 bv;
        if (gn + 3 < N) {
            bv = *(const float4*)&Bm[(size_t)(k0 + b_k) * N + gn];
        } else {
            bv.x = (gn + 0 < N) ? Bm[(size_t)(k0 + b_k) * N + gn + 0] : 0.f;
            bv.y = (gn + 1 < N) ? Bm[(size_t)(k0 + b_k) * N + gn + 1] : 0.f;
            bv.z = (gn + 2 < N) ? Bm[(size_t)(k0 + b_k) * N + gn + 2] : 0.f;
            bv.w = (gn + 3 < N) ? Bm[(size_t)(k0 + b_k) * N + gn + 3] : 0.f;
        }
        *(float4*)&Bs[b_k][b_n] = bv;

        __syncthreads();

        #pragma unroll
        for (int k = 0; k < 16; k++) {
            float4 a0 = *(const float4*)&As[k][ty * 8];
            float4 a1 = *(const float4*)&As[k][ty * 8 + 4];
            float4 b4 = *(const float4*)&Bs[k][tx * 4];
            float ar[8] = {a0.x, a0.y, a0.z, a0.w, a1.x, a1.y, a1.z, a1.w};
            float br[4] = {b4.x, b4.y, b4.z, b4.w};
            #pragma unroll
            for (int i = 0; i < 8; i++)
                #pragma unroll
                for (int j = 0; j < 4; j++)
                    acc[i][j] = fmaf(ar[i], br[j], acc[i][j]);
        }
        __syncthreads();
    }

    #pragma unroll
    for (int i = 0; i < 8; i++) {
        const int m = m0 + ty * 8 + i;
        #pragma unroll
        for (int j = 0; j < 4; j++) {
            const int nn = n0 + tx * 4 + j;
            if (nn >= N) continue;
            float vv = acc[i][j] + bias[nn];
            float ex = __expf(-vv);
            out[(size_t)m * N + nn] = __fdividef(1.0f, 1.0f + ex);
        }
    }
}

// ---------------------------------------------------------------------------
// Launch. Input order: x, u, W_enc, b_enc, W_dec, b_dec, prior
// Output: du [BZ] | z [BZ] | y [B*DIN]
// ---------------------------------------------------------------------------
extern "C" void kernel_launch(void* const* d_in, const int* in_sizes, int n_in,
                              void* d_out, int out_size)
{
    const float* x     = (const float*)d_in[0];
    const float* u     = (const float*)d_in[1];
    const float* W_enc = (const float*)d_in[2];
    const float* b_enc = (const float*)d_in[3];
    const float* W_dec = (const float*)d_in[4];
    const float* b_dec = (const float*)d_in[5];
    const float* prior = (const float*)d_in[6];

    float* out_du = (float*)d_out;
    float* out_z  = out_du + (size_t)BZ;
    float* out_y  = out_z  + (size_t)BZ;

    // 1) encoder split-K GEMM
    {
        dim3 grid(DZ / 64, BB / 128, KSPLIT);
        enc_gemm_splitk<<<grid, 256>>>(x, W_enc);
    }
    // 2) fused epilogue + exponential race -> du, z
    race_kernel<<<BZ / 256, 256>>>(u, b_enc, prior, out_du, out_z);

    // 3) decoder GEMM: y = sigmoid(z @ W_dec + b_dec)
    {
        dim3 grid((DIN + 63) / 64, BB / 128);
        dec_gemm<<<grid, 256>>>(out_z, W_dec, b_dec, out_y);
    }
}

// round 5
// speedup vs baseline: 1.8467x; 1.0032x over previous
#include <cuda_runtime.h>

// Problem dims
#define BB       4096
#define DIN      784
#define DZ       128
#define NTRIALS  256
#define BZ       (BB * DZ)
#define KSPLIT   7          // 49 K-tiles of 16 = 7 chunks x 7 tiles, exact

// Scratch (device globals => no allocations).
__device__ float g_part[KSPLIT][BZ];   // split-K partials for encoder

__device__ __forceinline__ float tanhf_fast(float x) {
    float y;
    asm("tanh.approx.f32 %0, %1;" : "=f"(y) : "f"(x));
    return y;
}

// ---------------------------------------------------------------------------
// Encoder split-K GEMM: g_part[c] = x[:, chunk] @ W_enc[chunk, :]
// BM=128, BN=128(=DZ), BK=16, 256 threads, 8x8 split fragments,
// double-buffered SMEM (1 syncthreads per K-tile). All dims exact.
// grid = (1, BB/128=32, KSPLIT=7)
// ---------------------------------------------------------------------------
__global__ __launch_bounds__(256)
void enc_gemm_splitk(const float* __restrict__ A,
                     const float* __restrict__ Bm)
{
    __shared__ float As[2][16][128];
    __shared__ float Bs[2][16][128];

    const int tid = threadIdx.x;
    const int tx  = tid & 15;          // n dir
    const int ty  = tid >> 4;          // m dir
    const int m0  = blockIdx.y * 128;
    const int chunk = blockIdx.z;

    // A tile: 128x16, per-thread 2 float4 (one row, 8 k's)
    const int a_m = tid >> 1;
    const int a_k = (tid & 1) * 8;
    // B tile: 16x128, per-thread 2 float4 (rows b_k and b_k+8)
    const int b_k = tid >> 5;          // 0..7
    const int b_c = (tid & 31) * 4;    // 0..124

    float acc[8][8];
    #pragma unroll
    for (int i = 0; i < 8; i++)
        #pragma unroll
        for (int j = 0; j < 8; j++) acc[i][j] = 0.f;

    const int t_base = chunk * 7;
    float4 av0, av1, bv0, bv1;

    // preload tile 0
    {
        const int k0 = t_base * 16;
        av0 = *(const float4*)&A[(size_t)(m0 + a_m) * DIN + k0 + a_k];
        av1 = *(const float4*)&A[(size_t)(m0 + a_m) * DIN + k0 + a_k + 4];
        bv0 = *(const float4*)&Bm[(size_t)(k0 + b_k) * DZ + b_c];
        bv1 = *(const float4*)&Bm[(size_t)(k0 + b_k + 8) * DZ + b_c];
    }
    As[0][a_k + 0][a_m] = av0.x; As[0][a_k + 1][a_m] = av0.y;
    As[0][a_k + 2][a_m] = av0.z; As[0][a_k + 3][a_m] = av0.w;
    As[0][a_k + 4][a_m] = av1.x; As[0][a_k + 5][a_m] = av1.y;
    As[0][a_k + 6][a_m] = av1.z; As[0][a_k + 7][a_m] = av1.w;
    *(float4*)&Bs[0][b_k][b_c]     = bv0;
    *(float4*)&Bs[0][b_k + 8][b_c] = bv1;
    __syncthreads();

    #pragma unroll 1
    for (int t = 0; t < 7; t++) {
        if (t < 6) {
            const int k0 = (t_base + t + 1) * 16;
            av0 = *(const float4*)&A[(size_t)(m0 + a_m) * DIN + k0 + a_k];
            av1 = *(const float4*)&A[(size_t)(m0 + a_m) * DIN + k0 + a_k + 4];
            bv0 = *(const float4*)&Bm[(size_t)(k0 + b_k) * DZ + b_c];
            bv1 = *(const float4*)&Bm[(size_t)(k0 + b_k + 8) * DZ + b_c];
        }
        const int cur = t & 1;
        #pragma unroll
        for (int k = 0; k < 16; k++) {
            float4 aA = *(const float4*)&As[cur][k][ty * 4];
            float4 aB = *(const float4*)&As[cur][k][64 + ty * 4];
            float4 bA = *(const float4*)&Bs[cur][k][tx * 4];
            float4 bB = *(const float4*)&Bs[cur][k][64 + tx * 4];
            float ar[8] = {aA.x, aA.y, aA.z, aA.w, aB.x, aB.y, aB.z, aB.w};
            float br[8] = {bA.x, bA.y, bA.z, bA.w, bB.x, bB.y, bB.z, bB.w};
            #pragma unroll
            for (int i = 0; i < 8; i++)
                #pragma unroll
                for (int j = 0; j < 8; j++)
                    acc[i][j] = fmaf(ar[i], br[j], acc[i][j]);
        }
        if (t < 6) {
            const int nxt = (t + 1) & 1;
            As[nxt][a_k + 0][a_m] = av0.x; As[nxt][a_k + 1][a_m] = av0.y;
            As[nxt][a_k + 2][a_m] = av0.z; As[nxt][a_k + 3][a_m] = av0.w;
            As[nxt][a_k + 4][a_m] = av1.x; As[nxt][a_k + 5][a_m] = av1.y;
            As[nxt][a_k + 6][a_m] = av1.z; As[nxt][a_k + 7][a_m] = av1.w;
            *(float4*)&Bs[nxt][b_k][b_c]     = bv0;
            *(float4*)&Bs[nxt][b_k + 8][b_c] = bv1;
        }
        __syncthreads();
    }

    float* dst = g_part[chunk];
    #pragma unroll
    for (int i = 0; i < 8; i++) {
        const int m = m0 + ((i < 4) ? (ty * 4 + i) : (64 + ty * 4 + i - 4));
        float4 vA = make_float4(acc[i][0], acc[i][1], acc[i][2], acc[i][3]);
        float4 vB = make_float4(acc[i][4], acc[i][5], acc[i][6], acc[i][7]);
        *(float4*)&dst[(size_t)m * DZ + tx * 4]      = vA;
        *(float4*)&dst[(size_t)m * DZ + 64 + tx * 4] = vB;
    }
}

// ---------------------------------------------------------------------------
// Fused encoder-epilogue + exponential race. One thread per (b,z).
// Software-pipelined (prefetch next 8 trials), warp-uniform early exit with a
// rate-aware geometric tail bound:
//   past exit, terms decay by ~exp(-1/rate) per trial => tail ~ s*rate.
//   Exit when s*min(255, 6*rate) <= 2e-4*zacc  (worst-lane tail <= 2e-4 rel).
// Base-2 math: cum = sum lg2(1-u); sigmoid(1-times)=0.5+0.5*tanh(0.5+a*cum),
// a = 0.5*ln2*inv_rate.
// ---------------------------------------------------------------------------
__global__ __launch_bounds__(256)
void race_kernel(const float* __restrict__ u,
                 const float* __restrict__ bias,
                 const float* __restrict__ prior,
                 float* __restrict__ out_du,
                 float* __restrict__ zout)
{
    const int i = blockIdx.x * blockDim.x + threadIdx.x;
    const int n = i & (DZ - 1);

    float v = g_part[0][i] + g_part[1][i] + g_part[2][i] + g_part[3][i]
            + g_part[4][i] + g_part[5][i] + g_part[6][i] + bias[n];
    float du = fminf(v, 5.0f);
    out_du[i] = du;
    float lr = fminf(du + fminf(prior[n], 5.0f), 5.0f);
    float rate = __expf(lr) + 1e-6f;
    float inv_rate = 1.0f / rate;
    const float a = 0.34657359f * inv_rate;            // 0.5*ln2/rate
    const float exit_f = fminf(255.0f, 6.0f * rate);   // geometric tail factor

    const float* up = u + i;

    float cum = 0.f, zacc = 0.f;
    float buf[8];
    #pragma unroll
    for (int j = 0; j < 8; j++) buf[j] = up[(size_t)j * BZ];

    #pragma unroll 1
    for (int t0 = 0; t0 < NTRIALS; t0 += 8) {
        float nbuf[8];
        if (t0 + 8 < NTRIALS) {
            #pragma unroll
            for (int j = 0; j < 8; j++)
                nbuf[j] = up[(size_t)(t0 + 8 + j) * BZ];
        }

        float s = 0.f;
        #pragma unroll
        for (int j = 0; j < 8; j++) {
            cum += __log2f(1.0f - buf[j]);          // negative, decreasing
            float h  = fmaf(cum, a, 0.5f);          // (1-times)/2
            s = fmaf(0.5f, tanhf_fast(h), 0.5f);    // sigmoid(1-times)
            zacc += s;
        }

        if (__all_sync(0xFFFFFFFFu, s * exit_f <= zacc * 2e-4f + 1e-30f))
            break;

        #pragma unroll
        for (int j = 0; j < 8; j++) buf[j] = nbuf[j];
    }
    zout[i] = zacc;
}

// ---------------------------------------------------------------------------
// Decoder GEMM: y = sigmoid(z @ W_dec + b_dec)
// BM=128, BN=128, BK=16, 256 threads, 8x8 split fragments, double-buffered.
// N=784 guarded (784 % 4 == 0 so float4 groups are all-or-nothing).
// grid = (7, 32)
// ---------------------------------------------------------------------------
__global__ __launch_bounds__(256)
void dec_gemm(const float* __restrict__ A,
              const float* __restrict__ Bm,
              const float* __restrict__ bias,
              float* __restrict__ out)
{
    const int N = DIN;
    __shared__ float As[2][16][128];
    __shared__ float Bs[2][16][128];

    const int tid = threadIdx.x;
    const int tx  = tid & 15;
    const int ty  = tid >> 4;
    const int m0  = blockIdx.y * 128;
    const int n0  = blockIdx.x * 128;

    const int a_m = tid >> 1;
    const int a_k = (tid & 1) * 8;
    const int b_k = tid >> 5;
    const int b_c = (tid & 31) * 4;

    float acc[8][8];
    #pragma unroll
    for (int i = 0; i < 8; i++)
        #pragma unroll
        for (int j = 0; j < 8; j++) acc[i][j] = 0.f;

    const int gn = n0 + b_c;
    float4 av0, av1, bv0, bv1;

    {
        av0 = *(const float4*)&A[(size_t)(m0 + a_m) * DZ + a_k];
        av1 = *(const float4*)&A[(size_t)(m0 + a_m) * DZ + a_k + 4];
        bv0 = make_float4(0.f, 0.f, 0.f, 0.f);
        bv1 = bv0;
        if (gn < N) {
            bv0 = *(const float4*)&Bm[(size_t)(b_k) * N + gn];
            bv1 = *(const float4*)&Bm[(size_t)(b_k + 8) * N + gn];
        }
    }
    As[0][a_k + 0][a_m] = av0.x; As[0][a_k + 1][a_m] = av0.y;
    As[0][a_k + 2][a_m] = av0.z; As[0][a_k + 3][a_m] = av0.w;
    As[0][a_k + 4][a_m] = av1.x; As[0][a_k + 5][a_m] = av1.y;
    As[0][a_k + 6][a_m] = av1.z; As[0][a_k + 7][a_m] = av1.w;
    *(float4*)&Bs[0][b_k][b_c]     = bv0;
    *(float4*)&Bs[0][b_k + 8][b_c] = bv1;
    __syncthreads();

    #pragma unroll 1
    for (int t = 0; t < 8; t++) {
        if (t < 7) {
            const int k0 = (t + 1) * 16;
            av0 = *(const float4*)&A[(size_t)(m0 + a_m) * DZ + k0 + a_k];
            av1 = *(const float4*)&A[(size_t)(m0 + a_m) * DZ + k0 + a_k + 4];
            bv0 = make_float4(0.f, 0.f, 0.f, 0.f);
            bv1 = bv0;
            if (gn < N) {
                bv0 = *(const float4*)&Bm[(size_t)(k0 + b_k) * N + gn];
                bv1 = *(const float4*)&Bm[(size_t)(k0 + b_k + 8) * N + gn];
            }
        }
        const int cur = t & 1;
        #pragma unroll
        for (int k = 0; k < 16; k++) {
            float4 aA = *(const float4*)&As[cur][k][ty * 4];
            float4 aB = *(const float4*)&As[cur][k][64 + ty * 4];
            float4 bA = *(const float4*)&Bs[cur][k][tx * 4];
            float4 bB = *(const float4*)&Bs[cur][k][64 + tx * 4];
            float ar[8] = {aA.x, aA.y, aA.z, aA.w, aB.x, aB.y, aB.z, aB.w};
            float br[8] = {bA.x, bA.y, bA.z, bA.w, bB.x, bB.y, bB.z, bB.w};
            #pragma unroll
            for (int i = 0; i < 8; i++)
                #pragma unroll
                for (int j = 0; j < 8; j++)
                    acc[i][j] = fmaf(ar[i], br[j], acc[i][j]);
        }
        if (t < 7) {
            const int nxt = (t + 1) & 1;
            As[nxt][a_k + 0][a_m] = av0.x; As[nxt][a_k + 1][a_m] = av0.y;
            As[nxt][a_k + 2][a_m] = av0.z; As[nxt][a_k + 3][a_m] = av0.w;
            As[nxt][a_k + 4][a_m] = av1.x; As[nxt][a_k + 5][a_m] = av1.y;
            As[nxt][a_k + 6][a_m] = av1.z; As[nxt][a_k + 7][a_m] = av1.w;
            *(float4*)&Bs[nxt][b_k][b_c]     = bv0;
            *(float4*)&Bs[nxt][b_k + 8][b_c] = bv1;
        }
        __syncthreads();
    }

    #pragma unroll
    for (int i = 0; i < 8; i++) {
        const int m = m0 + ((i < 4) ? (ty * 4 + i) : (64 + ty * 4 + i - 4));
        #pragma unroll
        for (int half = 0; half < 2; half++) {
            const int nn = n0 + half * 64 + tx * 4;
            if (nn >= N) continue;
            float4 r;
            float* accp = &acc[i][half * 4];
            r.x = accp[0] + bias[nn + 0];
            r.y = accp[1] + bias[nn + 1];
            r.z = accp[2] + bias[nn + 2];
            r.w = accp[3] + bias[nn + 3];
            r.x = __fdividef(1.0f, 1.0f + __expf(-r.x));
            r.y = __fdividef(1.0f, 1.0f + __expf(-r.y));
            r.z = __fdividef(1.0f, 1.0f + __expf(-r.z));
            r.w = __fdividef(1.0f, 1.0f + __expf(-r.w));
            *(float4*)&out[(size_t)m * N + nn] = r;
        }
    }
}

// ---------------------------------------------------------------------------
// Launch. Input order: x, u, W_enc, b_enc, W_dec, b_dec, prior
// Output: du [BZ] | z [BZ] | y [B*DIN]
// ---------------------------------------------------------------------------
extern "C" void kernel_launch(void* const* d_in, const int* in_sizes, int n_in,
                              void* d_out, int out_size)
{
    const float* x     = (const float*)d_in[0];
    const float* u     = (const float*)d_in[1];
    const float* W_enc = (const float*)d_in[2];
    const float* b_enc = (const float*)d_in[3];
    const float* W_dec = (const float*)d_in[4];
    const float* b_dec = (const float*)d_in[5];
    const float* prior = (const float*)d_in[6];

    float* out_du = (float*)d_out;
    float* out_z  = out_du + (size_t)BZ;
    float* out_y  = out_z  + (size_t)BZ;

    // 1) encoder split-K GEMM
    {
        dim3 grid(1, BB / 128, KSPLIT);
        enc_gemm_splitk<<<grid, 256>>>(x, W_enc);
    }
    // 2) fused epilogue + exponential race -> du, z
    race_kernel<<<BZ / 256, 256>>>(u, b_enc, prior, out_du, out_z);

    // 3) decoder GEMM: y = sigmoid(z @ W_dec + b_dec)
    {
        dim3 grid((DIN + 127) / 128, BB / 128);
        dec_gemm<<<grid, 256>>>(out_z, W_dec, b_dec, out_y);
    }
}